// round 7
// baseline (speedup 1.0000x reference)
#include <cuda_runtime.h>
#include <math.h>
#include <stdint.h>

#define LLATT 16
#define UU    512
#define NB    4            // batches per group
#define CL    2            // CTAs per cluster (unit split)
#define USL   256          // units per CTA
#define NTHR  512
#define NCTA  128

typedef unsigned long long ull;

struct SM {
    ull   hbuf[2][UU][2];        // [buf][global unit][bpair]       16 KB
    ull   states[8][UU][2];      // last 8 scan positions            64 KB
    ull   vrow[LLATT][USL][2];   // vertical term per column         64 KB
    ull   pred[4][USL][2];       // h-GEMV k-slice partials          16 KB
    float winh[2][UU];
    float winv[2][UU];
    float wout[UU][2];
    float bcarry[UU];
    float z[NB][2];
    float logp[NB];
    float bout0, bout1;
    int   xs[NB][LLATT * LLATT];
    ull   bar1;
};

__device__ __forceinline__ ull pk2(float lo, float hi) {
    ull r; asm("mov.b64 %0, {%1, %2};" : "=l"(r) : "f"(lo), "f"(hi)); return r;
}
__device__ __forceinline__ void upk2(ull v, float& lo, float& hi) {
    asm("mov.b64 {%0, %1}, %2;" : "=f"(lo), "=f"(hi) : "l"(v));
}
__device__ __forceinline__ void fma2(ull& acc, ull a, ull b) {
    asm("fma.rn.f32x2 %0, %1, %2, %0;" : "+l"(acc) : "l"(a), "l"(b));
}
__device__ __forceinline__ ull add2(ull a, ull b) {
    ull r; asm("add.rn.f32x2 %0, %1, %2;" : "=l"(r) : "l"(a), "l"(b)); return r;
}
__device__ __forceinline__ uint32_t smem_u32(const void* p) {
    return (uint32_t)__cvta_generic_to_shared(p);
}
__device__ __forceinline__ uint32_t mapa_rank(uint32_t a, uint32_t r) {
    uint32_t o; asm("mapa.shared::cluster.u32 %0, %1, %2;" : "=r"(o) : "r"(a), "r"(r));
    return o;
}
__device__ __forceinline__ void st_cl64(uint32_t addr, ull v) {
    asm volatile("st.shared::cluster.b64 [%0], %1;" :: "r"(addr), "l"(v) : "memory");
}
__device__ __forceinline__ void mbar_init(uint32_t addr, uint32_t cnt) {
    asm volatile("mbarrier.init.shared.b64 [%0], %1;" :: "r"(addr), "r"(cnt) : "memory");
}
__device__ __forceinline__ void mbar_arrive_remote(uint32_t addr) {
    asm volatile("mbarrier.arrive.release.cluster.shared::cluster.b64 _, [%0];"
                 :: "r"(addr) : "memory");
}
__device__ __forceinline__ void mbar_wait_parity(uint32_t addr, uint32_t parity) {
    asm volatile(
        "{\n\t.reg .pred P;\n\t"
        "WLP_%=:\n\t"
        "mbarrier.try_wait.parity.acquire.cluster.shared::cta.b64 P, [%0], %1, 0x989680;\n\t"
        "@P bra.uni WDN_%=;\n\t"
        "bra.uni WLP_%=;\n\t"
        "WDN_%=:\n\t}"
        :: "r"(addr), "r"(parity) : "memory");
}
#define CLUSTER_ARRIVE() asm volatile("barrier.cluster.arrive.aligned;" ::: "memory")
#define CLUSTER_WAIT()   asm volatile("barrier.cluster.wait.aligned;"   ::: "memory")

__global__ void __launch_bounds__(NTHR, 1) __cluster_dims__(CL, 1, 1)
rnn2d_kernel(const int* __restrict__ x,
             const float* __restrict__ Winh, const float* __restrict__ Winv,
             const float* __restrict__ Wch,  const float* __restrict__ bch,
             const float* __restrict__ Wcv,
             const float* __restrict__ Wout, const float* __restrict__ bout,
             float* __restrict__ out)
{
    extern __shared__ char smraw[];
    SM& sm = *reinterpret_cast<SM*>(smraw);
    const int tid = threadIdx.x;
    uint32_t rank;
    asm("mov.u32 %0, %%cluster_ctarank;" : "=r"(rank));
    const int grp = blockIdx.x >> 1;

    // ---------------- prologue ----------------
    for (int idx = tid; idx < 2 * UU; idx += NTHR) {
        ((float*)sm.winh)[idx] = Winh[idx];
        ((float*)sm.winv)[idx] = Winv[idx];
        ((float*)sm.wout)[idx] = Wout[idx];
    }
    for (int idx = tid; idx < UU; idx += NTHR) sm.bcarry[idx] = bch[idx];
    for (int idx = tid; idx < NB * LLATT * LLATT; idx += NTHR)
        ((int*)sm.xs)[idx] = x[grp * NB * LLATT * LLATT + idx];
    if (tid < NB) sm.logp[tid] = 0.f;
    if (tid == 0) {
        sm.bout0 = bout[0]; sm.bout1 = bout[1];
        mbar_init(smem_u32(&sm.bar1), 256);   // 256 pusher arrivals from peer
    }
    __syncthreads();
    CLUSTER_ARRIVE(); CLUSTER_WAIT();

    // ---- mappings ----
    // h-GEMV: 4 k-slices x 128 unit-pairs
    const int ks  = tid >> 7;                 // k-slice (128 k each)
    const int tu2 = tid & 127;                // unit pair in CTA slice
    const float2* __restrict__ WchP =
        reinterpret_cast<const float2*>(Wch) + (int)rank * 128 + tu2;
    // v-event: 2 k-halves x 2 col-halves x 128 unit-pairs
    const int vkh = (tid >> 7) & 1;
    const int vch = tid >> 8;
    const int vup = tid & 127;
    const float2* __restrict__ WcvP =
        reinterpret_cast<const float2*>(Wcv) + (int)rank * 128 + vup;
    // finalize: 1 unit x 1 bpair
    const int ul = tid >> 1;
    const int bh = tid & 1;
    const int ug = (int)rank * USL + ul;

    const uint32_t bar_loc  = smem_u32(&sm.bar1);
    const uint32_t bar_rem  = mapa_rank(bar_loc, rank ^ 1u);
    const uint32_t hbuf_rem = mapa_rank(smem_u32(&sm.hbuf[0][0][0]), rank ^ 1u);
    const uint32_t st_rem   = mapa_rank(smem_u32(&sm.states[0][0][0]), rank ^ 1u);

    int n = 0;
    for (int i = 0; i < LLATT; ++i) {
        const int d = (i & 1) ? -1 : 1;
        for (int j = 0; j < LLATT; ++j, ++n) {
            const int c   = (d == 1) ? j : (LLATT - 1 - j);
            const int buf = n & 1;
            const int pb  = buf ^ 1;
            const int slot = j & 7;

            // ---- 8-column vertical GEMM events (31 total) ----
            if ((j == 8 && i < 15) || (j == 0 && i > 0)) {
                __syncthreads();
                const int rsrc = (j == 8) ? i : i - 1;
                const int p0   = (j == 8) ? 0 : 8;
                int col[4], slt[4];
#pragma unroll
                for (int t = 0; t < 4; ++t) {
                    const int p = p0 + vch * 4 + t;
                    slt[t] = p & 7;
                    col[t] = (rsrc & 1) ? (15 - p) : p;
                }
                ull A[4][2][2];                    // [pos][unit][bpair]
#pragma unroll
                for (int t = 0; t < 4; ++t)
#pragma unroll
                    for (int u = 0; u < 2; ++u) { A[t][u][0] = 0ull; A[t][u][1] = 0ull; }
                const int k0 = vkh * 256;
                float2 wb[2][8];
#pragma unroll
                for (int q = 0; q < 8; ++q) wb[0][q] = WcvP[(k0 + q) * 256];
#pragma unroll 1
                for (int kk = 0; kk < 256; kk += 8) {
                    const int cb = (kk >> 3) & 1;
                    if (kk + 8 < 256) {
#pragma unroll
                        for (int q = 0; q < 8; ++q)
                            wb[cb ^ 1][q] = WcvP[(k0 + kk + 8 + q) * 256];
                    }
#pragma unroll
                    for (int q = 0; q < 8; ++q) {
                        const int k = k0 + kk + q;
                        const float2 w = wb[cb][q];
                        const ull wx = pk2(w.x, w.x);
                        const ull wy = pk2(w.y, w.y);
#pragma unroll
                        for (int t = 0; t < 4; ++t) {
                            const ulonglong2 sv =
                                *(const ulonglong2*)&sm.states[slt[t]][k][0];
                            fma2(A[t][0][0], sv.x, wx); fma2(A[t][0][1], sv.y, wx);
                            fma2(A[t][1][0], sv.x, wy); fma2(A[t][1][1], sv.y, wy);
                        }
                    }
                }
                const int lu = 2 * vup;
                if (vkh == 0) {
#pragma unroll
                    for (int t = 0; t < 4; ++t)
#pragma unroll
                        for (int u = 0; u < 2; ++u) {
                            ulonglong2 tv; tv.x = A[t][u][0]; tv.y = A[t][u][1];
                            *(ulonglong2*)&sm.vrow[col[t]][lu + u][0] = tv;
                        }
                }
                __syncthreads();
                if (vkh == 1) {
#pragma unroll
                    for (int t = 0; t < 4; ++t)
#pragma unroll
                        for (int u = 0; u < 2; ++u) {
                            ull* vp = &sm.vrow[col[t]][lu + u][0];
                            vp[0] = add2(vp[0], A[t][u][0]);
                            vp[1] = add2(vp[1], A[t][u][1]);
                        }
                }
                __syncthreads();
                CLUSTER_ARRIVE(); CLUSTER_WAIT();   // fence event reads vs slot reuse
            }

            // ---- h @ W_carry_h: 4-way k-split, double-buffered ----
            if (j > 0) {
                ull a00 = 0ull, a01 = 0ull, a10 = 0ull, a11 = 0ull;
                const int k0 = ks * 128;
                const ull (*__restrict__ hb)[2] = sm.hbuf[pb];
                float2 wb[2][8];
#pragma unroll
                for (int q = 0; q < 8; ++q) wb[0][q] = WchP[(k0 + q) * 256];
#pragma unroll 1
                for (int kk = 0; kk < 128; kk += 8) {
                    const int cb = (kk >> 3) & 1;
                    if (kk + 8 < 128) {
#pragma unroll
                        for (int q = 0; q < 8; ++q)
                            wb[cb ^ 1][q] = WchP[(k0 + kk + 8 + q) * 256];
                    }
#pragma unroll
                    for (int q = 0; q < 8; ++q) {
                        const ulonglong2 hv =
                            *(const ulonglong2*)&hb[k0 + kk + q][0];
                        const float2 w = wb[cb][q];
                        const ull wx = pk2(w.x, w.x);
                        const ull wy = pk2(w.y, w.y);
                        fma2(a00, hv.x, wx); fma2(a01, hv.y, wx);
                        fma2(a10, hv.x, wy); fma2(a11, hv.y, wy);
                    }
                }
                ulonglong2 t0, t1;
                t0.x = a00; t0.y = a01;
                t1.x = a10; t1.y = a11;
                *(ulonglong2*)&sm.pred[ks][2 * tu2][0]     = t0;
                *(ulonglong2*)&sm.pred[ks][2 * tu2 + 1][0] = t1;
            }
            __syncthreads();   // S1

            // ---- finalize: 1 unit x 1 bpair per thread ----
            {
                ull a = 0ull;
                if (j > 0) {
                    a = add2(add2(sm.pred[0][ul][bh], sm.pred[1][ul][bh]),
                             add2(sm.pred[2][ul][bh], sm.pred[3][ul][bh]));
                }
                if (i > 0) a = add2(a, sm.vrow[c][ul][bh]);
                float v0, v1;
                upk2(a, v0, v1);
                const float base = sm.bcarry[ug];
                v0 += base; v1 += base;
                const int b0 = 2 * bh, b1 = b0 + 1;
                if (j > 0) {
                    const int cp = c - d;
                    v0 += sm.winh[sm.xs[b0][i * LLATT + cp]][ug];
                    v1 += sm.winh[sm.xs[b1][i * LLATT + cp]][ug];
                }
                if (i > 0) {
                    v0 += sm.winv[sm.xs[b0][(i - 1) * LLATT + c]][ug];
                    v1 += sm.winv[sm.xs[b1][(i - 1) * LLATT + c]][ug];
                }
                v0 = v0 > 0.f ? v0 : expm1f(v0);
                v1 = v1 > 0.f ? v1 : expm1f(v1);
                const ull e = pk2(v0, v1);
                sm.hbuf[buf][ug][bh]     = e;
                sm.states[slot][ug][bh]  = e;
            }
            __syncthreads();   // S2: local slice complete

            // ---- exchange: even threads push both bpairs of their unit ----
            if (bh == 0) {
                const ull e0 = sm.hbuf[buf][ug][0];
                const ull e1 = sm.hbuf[buf][ug][1];
                const uint32_t ho = (uint32_t)(((buf * UU + ug) * 2) * 8);
                const uint32_t so = (uint32_t)(((slot * UU + ug) * 2) * 8);
                st_cl64(hbuf_rem + ho,     e0);
                st_cl64(hbuf_rem + ho + 8, e1);
                st_cl64(st_rem + so,     e0);
                st_cl64(st_rem + so + 8, e1);
                mbar_arrive_remote(bar_rem);
            }
            mbar_wait_parity(bar_loc, (uint32_t)(n & 1));   // peer slice arrived

            // ---- logits: warps 0-7, full h (local after wait) ----
            {
                const int w = tid >> 5, lane = tid & 31;
                if (w < 8) {
                    const int b = w >> 1, dc = w & 1;
                    const int bp = b >> 1, hi = b & 1;
                    float zz = 0.f;
#pragma unroll
                    for (int q = 0; q < 16; ++q) {
                        const int u = lane + q * 32;
                        float lo2, hi2;
                        upk2(sm.hbuf[buf][u][bp], lo2, hi2);
                        zz += (hi ? hi2 : lo2) * sm.wout[u][dc];
                    }
#pragma unroll
                    for (int off = 16; off; off >>= 1)
                        zz += __shfl_down_sync(0xffffffffu, zz, off);
                    if (lane == 0) sm.z[b][dc] = zz;
                }
            }
            __syncthreads();   // S3
            if (tid < NB) {
                const float z0 = sm.z[tid][0] + sm.bout0;
                const float z1 = sm.z[tid][1] + sm.bout1;
                const int s = sm.xs[tid][i * LLATT + c];
                const float m = fmaxf(z0, z1);
                const float lse = m + logf(expf(z0 - m) + expf(z1 - m));
                sm.logp[tid] += (s ? z1 : z0) - lse;
            }
        }
    }
    __syncthreads();
    if (rank == 0 && tid < NB) out[grp * NB + tid] = sm.logp[tid];
    CLUSTER_ARRIVE(); CLUSTER_WAIT();
}

extern "C" void kernel_launch(void* const* d_in, const int* in_sizes, int n_in,
                              void* d_out, int out_size)
{
    const int*   x    = (const int*)d_in[0];
    const float* Winh = (const float*)d_in[1];
    const float* Winv = (const float*)d_in[2];
    const float* Wch  = (const float*)d_in[3];
    const float* bch  = (const float*)d_in[4];
    const float* Wcv  = (const float*)d_in[5];
    const float* Wout = (const float*)d_in[6];
    const float* bout = (const float*)d_in[7];
    float* out = (float*)d_out;

    const int smem = (int)sizeof(SM);
    cudaFuncSetAttribute(rnn2d_kernel,
                         cudaFuncAttributeMaxDynamicSharedMemorySize, smem);
    rnn2d_kernel<<<NCTA, NTHR, smem>>>(x, Winh, Winv, Wch, bch, Wcv,
                                       Wout, bout, out);
}

// round 8
// speedup vs baseline: 1.2898x; 1.2898x over previous
#include <cuda_runtime.h>
#include <cuda_bf16.h>
#include <math.h>
#include <stdint.h>

#define LLATT 16
#define UU    512
#define NB    4            // batches per group
#define CL    2            // CTAs per cluster (unit split)
#define USL   256          // units per CTA
#define NTHR  256
#define NGRP  64
#define NCTA  128

typedef unsigned long long ull;

// packed bf16 W_carry_h: idx = k*128 + t holds units 4t..4t+3 for row k
__device__ ull g_wch_bf[UU * UU / 4];

struct SM {
    ull   hbuf[2][UU][2];        // [buf][global unit][bpair]       16 KB
    ull   states[8][UU][2];      // last 8 scan positions            64 KB
    ull   vrow[LLATT][USL][2];   // vertical term per column         64 KB
    ull   pred[4][USL][2];       // h-GEMV k-slice partials          16 KB
    float winh[2][UU];
    float winv[2][UU];
    float wout[UU][2];
    float bcarry[UU];
    float z[NB][2];
    float logp[NB];
    float bout0, bout1;
    int   xs[NB][LLATT * LLATT];
    ull   bar1;
};

__device__ __forceinline__ ull pk2(float lo, float hi) {
    ull r; asm("mov.b64 %0, {%1, %2};" : "=l"(r) : "f"(lo), "f"(hi)); return r;
}
__device__ __forceinline__ ull pkdup(unsigned r) {
    ull o; asm("mov.b64 %0, {%1, %1};" : "=l"(o) : "r"(r)); return o;
}
__device__ __forceinline__ void upk2(ull v, float& lo, float& hi) {
    asm("mov.b64 {%0, %1}, %2;" : "=f"(lo), "=f"(hi) : "l"(v));
}
__device__ __forceinline__ void fma2(ull& acc, ull a, ull b) {
    asm("fma.rn.f32x2 %0, %1, %2, %0;" : "+l"(acc) : "l"(a), "l"(b));
}
__device__ __forceinline__ ull add2(ull a, ull b) {
    ull r; asm("add.rn.f32x2 %0, %1, %2;" : "=l"(r) : "l"(a), "l"(b)); return r;
}
__device__ __forceinline__ uint32_t smem_u32(const void* p) {
    return (uint32_t)__cvta_generic_to_shared(p);
}
__device__ __forceinline__ uint32_t mapa_rank(uint32_t a, uint32_t r) {
    uint32_t o; asm("mapa.shared::cluster.u32 %0, %1, %2;" : "=r"(o) : "r"(a), "r"(r));
    return o;
}
__device__ __forceinline__ void st_cl64(uint32_t addr, ull v) {
    asm volatile("st.shared::cluster.b64 [%0], %1;" :: "r"(addr), "l"(v) : "memory");
}
__device__ __forceinline__ void mbar_init(uint32_t addr, uint32_t cnt) {
    asm volatile("mbarrier.init.shared.b64 [%0], %1;" :: "r"(addr), "r"(cnt) : "memory");
}
__device__ __forceinline__ void mbar_arrive_remote(uint32_t addr) {
    asm volatile("mbarrier.arrive.release.cluster.shared::cluster.b64 _, [%0];"
                 :: "r"(addr) : "memory");
}
__device__ __forceinline__ void mbar_wait_parity(uint32_t addr, uint32_t parity) {
    asm volatile(
        "{\n\t.reg .pred P;\n\t"
        "WLP_%=:\n\t"
        "mbarrier.try_wait.parity.acquire.cluster.shared::cta.b64 P, [%0], %1, 0x989680;\n\t"
        "@P bra.uni WDN_%=;\n\t"
        "bra.uni WLP_%=;\n\t"
        "WDN_%=:\n\t}"
        :: "r"(addr), "r"(parity) : "memory");
}
#define CLUSTER_ARRIVE() asm volatile("barrier.cluster.arrive.aligned;" ::: "memory")
#define CLUSTER_WAIT()   asm volatile("barrier.cluster.wait.aligned;"   ::: "memory")

// one-time (per launch) conversion of W_carry_h to packed bf16
__global__ void prep_wch(const float* __restrict__ Wch) {
    const int idx = blockIdx.x * blockDim.x + threadIdx.x;   // 0 .. 65535
    const int k = idx >> 7, t = idx & 127;
    const float* p = Wch + k * UU + 4 * t;
    __nv_bfloat162 lo = __floats2bfloat162_rn(p[0], p[1]);
    __nv_bfloat162 hi = __floats2bfloat162_rn(p[2], p[3]);
    const unsigned ulo = *reinterpret_cast<unsigned*>(&lo);
    const unsigned uhi = *reinterpret_cast<unsigned*>(&hi);
    g_wch_bf[idx] = ((ull)uhi << 32) | ulo;
}

// 64-k slice of the h-GEMV with bf16 weights, double-buffered prefetch
__device__ __forceinline__ void gemv64bf(ull acc[4][2], const ull* __restrict__ wp,
                                         const ull (*__restrict__ hb)[2], int kbase)
{
    ull wb[2][8];
#pragma unroll
    for (int q = 0; q < 8; ++q) wb[0][q] = wp[(kbase + q) * 128];
#pragma unroll 1
    for (int kk = 0; kk < 64; kk += 8) {
        const int cb = (kk >> 3) & 1;
        if (kk + 8 < 64) {
#pragma unroll
            for (int q = 0; q < 8; ++q) wb[cb ^ 1][q] = wp[(kbase + kk + 8 + q) * 128];
        }
#pragma unroll
        for (int q = 0; q < 8; ++q) {
            const ulonglong2 hv = *(const ulonglong2*)&hb[kbase + kk + q][0];
            const ull w = wb[cb][q];
            const unsigned lo = (unsigned)w;
            const unsigned hi = (unsigned)(w >> 32);
            const ull w0 = pkdup(lo << 16);
            const ull w1 = pkdup(lo & 0xffff0000u);
            const ull w2 = pkdup(hi << 16);
            const ull w3 = pkdup(hi & 0xffff0000u);
            fma2(acc[0][0], hv.x, w0); fma2(acc[0][1], hv.y, w0);
            fma2(acc[1][0], hv.x, w1); fma2(acc[1][1], hv.y, w1);
            fma2(acc[2][0], hv.x, w2); fma2(acc[2][1], hv.y, w2);
            fma2(acc[3][0], hv.x, w3); fma2(acc[3][1], hv.y, w3);
        }
    }
}

__global__ void __launch_bounds__(NTHR, 1) __cluster_dims__(CL, 1, 1)
rnn2d_kernel(const int* __restrict__ x,
             const float* __restrict__ Winh, const float* __restrict__ Winv,
             const float* __restrict__ Wch,  const float* __restrict__ bch,
             const float* __restrict__ Wcv,
             const float* __restrict__ Wout, const float* __restrict__ bout,
             float* __restrict__ out)
{
    extern __shared__ char smraw[];
    SM& sm = *reinterpret_cast<SM*>(smraw);
    const int tid = threadIdx.x;
    uint32_t rank;
    asm("mov.u32 %0, %%cluster_ctarank;" : "=r"(rank));
    const int grp = blockIdx.x >> 1;

    // ---------------- prologue ----------------
    for (int idx = tid; idx < 2 * UU; idx += NTHR) {
        ((float*)sm.winh)[idx] = Winh[idx];
        ((float*)sm.winv)[idx] = Winv[idx];
        ((float*)sm.wout)[idx] = Wout[idx];
    }
    for (int idx = tid; idx < UU; idx += NTHR) sm.bcarry[idx] = bch[idx];
    for (int idx = tid; idx < NB * LLATT * LLATT; idx += NTHR)
        ((int*)sm.xs)[idx] = x[grp * NB * LLATT * LLATT + idx];
    if (tid < NB) sm.logp[tid] = 0.f;
    if (tid == 0) {
        sm.bout0 = bout[0]; sm.bout1 = bout[1];
        mbar_init(smem_u32(&sm.bar1), 128);   // 128 writer arrivals from peer
    }
    __syncthreads();
    CLUSTER_ARRIVE(); CLUSTER_WAIT();          // publish mbarrier init

    const int ks  = tid >> 6;                  // k-slice (4 x 64k per half)
    const int tu4 = tid & 63;                  // 4-unit group in CTA slice
    const ull* __restrict__ WchP = g_wch_bf + (int)rank * 64 + tu4;
    // v-event mapping: tu2 -> 2 units, kh -> k-half
    const int kh  = tid >> 7;
    const int tu2 = tid & 127;
    const float2* __restrict__ WcvP =
        reinterpret_cast<const float2*>(Wcv) + (int)rank * 128 + tu2;

    const uint32_t bar_loc  = smem_u32(&sm.bar1);
    const uint32_t bar_rem  = mapa_rank(bar_loc, rank ^ 1u);
    const uint32_t hbuf_rem = mapa_rank(smem_u32(&sm.hbuf[0][0][0]), rank ^ 1u);
    const uint32_t st_rem   = mapa_rank(smem_u32(&sm.states[0][0][0]), rank ^ 1u);

    int n = 0;
    for (int i = 0; i < LLATT; ++i) {
        const int d = (i & 1) ? -1 : 1;
        for (int j = 0; j < LLATT; ++j, ++n) {
            const int c   = (d == 1) ? j : (LLATT - 1 - j);
            const int buf = n & 1;
            const int pb  = buf ^ 1;

            // ---- 8-column vertical GEMM events (31 total), fp32 weights ----
            if ((j == 8 && i < 15) || (j == 0 && i > 0)) {
                __syncthreads();
                const int i_src = (j == 8) ? i : i - 1;
                const int p0    = (j == 8) ? 0 : 8;
                ull A[8][2][2];
#pragma unroll
                for (int p = 0; p < 8; ++p)
#pragma unroll
                    for (int q = 0; q < 2; ++q) { A[p][q][0] = 0ull; A[p][q][1] = 0ull; }
                float2 wb[2][8];
#pragma unroll
                for (int q = 0; q < 8; ++q) wb[0][q] = WcvP[(kh * 256 + q) * 256];
#pragma unroll 1
                for (int kk = 0; kk < 256; kk += 8) {
                    const int cb = (kk >> 3) & 1;
                    if (kk + 8 < 256) {
#pragma unroll
                        for (int q = 0; q < 8; ++q)
                            wb[cb ^ 1][q] = WcvP[(kh * 256 + kk + 8 + q) * 256];
                    }
#pragma unroll
                    for (int q = 0; q < 8; ++q) {
                        const int k = kh * 256 + kk + q;
                        const float2 w = wb[cb][q];
                        const ull wx = pk2(w.x, w.x);
                        const ull wy = pk2(w.y, w.y);
#pragma unroll
                        for (int p = 0; p < 8; ++p) {
                            const ulonglong2 sv = *(const ulonglong2*)&sm.states[p][k][0];
                            fma2(A[p][0][0], sv.x, wx); fma2(A[p][0][1], sv.y, wx);
                            fma2(A[p][1][0], sv.x, wy); fma2(A[p][1][1], sv.y, wy);
                        }
                    }
                }
                const int lu0 = 2 * tu2;
                if (kh == 0) {
#pragma unroll
                    for (int p = 0; p < 8; ++p) {
                        const int col = (i_src & 1) ? 15 - (p0 + p) : (p0 + p);
                        sm.vrow[col][lu0][0] = A[p][0][0];
                        sm.vrow[col][lu0][1] = A[p][0][1];
                        sm.vrow[col][lu0 + 1][0] = A[p][1][0];
                        sm.vrow[col][lu0 + 1][1] = A[p][1][1];
                    }
                }
                __syncthreads();
                if (kh == 1) {
#pragma unroll
                    for (int p = 0; p < 8; ++p) {
                        const int col = (i_src & 1) ? 15 - (p0 + p) : (p0 + p);
                        sm.vrow[col][lu0][0] = add2(sm.vrow[col][lu0][0], A[p][0][0]);
                        sm.vrow[col][lu0][1] = add2(sm.vrow[col][lu0][1], A[p][0][1]);
                        sm.vrow[col][lu0 + 1][0] = add2(sm.vrow[col][lu0 + 1][0], A[p][1][0]);
                        sm.vrow[col][lu0 + 1][1] = add2(sm.vrow[col][lu0 + 1][1], A[p][1][1]);
                    }
                }
                __syncthreads();
                CLUSTER_ARRIVE(); CLUSTER_WAIT();   // fence GEMM vs slot reuse
            }

            // ---- h @ W_carry_h over both k-halves (bf16 weights) ----
            if (j > 0) {
                ull acc[4][2];
#pragma unroll
                for (int q = 0; q < 4; ++q) { acc[q][0] = 0ull; acc[q][1] = 0ull; }
                gemv64bf(acc, WchP, sm.hbuf[pb], (int)rank * 256 + ks * 64);
                gemv64bf(acc, WchP, sm.hbuf[pb], ((int)rank ^ 1) * 256 + ks * 64);
#pragma unroll
                for (int q = 0; q < 4; ++q) {
                    ulonglong2 t; t.x = acc[q][0]; t.y = acc[q][1];
                    *(ulonglong2*)&sm.pred[ks][4 * tu4 + q][0] = t;
                }
            }
            __syncthreads();   // S1

            // ---- finalize: 1 unit per thread ----
            {
                const int ul = tid;
                const int ug = (int)rank * USL + ul;
                ull a0 = 0ull, a1 = 0ull;
                if (j > 0) {
                    const ulonglong2 t0 = *(const ulonglong2*)&sm.pred[0][ul][0];
                    const ulonglong2 t1 = *(const ulonglong2*)&sm.pred[1][ul][0];
                    const ulonglong2 t2 = *(const ulonglong2*)&sm.pred[2][ul][0];
                    const ulonglong2 t3 = *(const ulonglong2*)&sm.pred[3][ul][0];
                    a0 = add2(add2(t0.x, t1.x), add2(t2.x, t3.x));
                    a1 = add2(add2(t0.y, t1.y), add2(t2.y, t3.y));
                }
                if (i > 0) {
                    const ulonglong2 vr = *(const ulonglong2*)&sm.vrow[c][ul][0];
                    a0 = add2(a0, vr.x); a1 = add2(a1, vr.y);
                }
                float v[NB];
                upk2(a0, v[0], v[1]); upk2(a1, v[2], v[3]);
                const float base = sm.bcarry[ug];
                int sh[NB], sv[NB];
                if (j > 0) {
                    const int cp = c - d;
#pragma unroll
                    for (int b = 0; b < NB; ++b) sh[b] = sm.xs[b][i * LLATT + cp];
                }
                if (i > 0) {
#pragma unroll
                    for (int b = 0; b < NB; ++b) sv[b] = sm.xs[b][(i - 1) * LLATT + c];
                }
#pragma unroll
                for (int b = 0; b < NB; ++b) {
                    float t = v[b] + base;
                    if (j > 0) t += sm.winh[sh[b]][ug];
                    if (i > 0) t += sm.winv[sv[b]][ug];
                    v[b] = t > 0.f ? t : expm1f(t);
                }
                const ull e0 = pk2(v[0], v[1]);
                const ull e1 = pk2(v[2], v[3]);
                const int slot = j & 7;
                sm.hbuf[buf][ug][0] = e0;    sm.hbuf[buf][ug][1] = e1;
                sm.states[slot][ug][0] = e0; sm.states[slot][ug][1] = e1;
                const uint32_t ho = (uint32_t)(((buf * UU + ug) * 2) * 8);
                st_cl64(hbuf_rem + ho,     e0);
                st_cl64(hbuf_rem + ho + 8, e1);
                const uint32_t so = (uint32_t)(((slot * UU + ug) * 2) * 8);
                st_cl64(st_rem + so,     e0);
                st_cl64(st_rem + so + 8, e1);
                if (tid < 128) mbar_arrive_remote(bar_rem);
            }
            __syncthreads();   // S2
            mbar_wait_parity(bar_loc, (uint32_t)(n & 1));  // peer slice arrived

            // ---- logits: warp w -> (batch w>>1, class w&1), full local h ----
            {
                const int w = tid >> 5, lane = tid & 31;
                const int b = w >> 1, dc = w & 1;
                const int bp = b >> 1, hi = b & 1;
                float zz = 0.f;
#pragma unroll
                for (int q = 0; q < 16; ++q) {
                    const int u = lane + q * 32;
                    float lo2, hi2;
                    upk2(sm.hbuf[buf][u][bp], lo2, hi2);
                    zz += (hi ? hi2 : lo2) * sm.wout[u][dc];
                }
#pragma unroll
                for (int off = 16; off; off >>= 1)
                    zz += __shfl_down_sync(0xffffffffu, zz, off);
                if (lane == 0) sm.z[b][dc] = zz;
            }
            __syncthreads();   // S3
            if (tid < NB) {
                const float z0 = sm.z[tid][0] + sm.bout0;
                const float z1 = sm.z[tid][1] + sm.bout1;
                const int s = sm.xs[tid][i * LLATT + c];
                const float m = fmaxf(z0, z1);
                const float lse = m + logf(expf(z0 - m) + expf(z1 - m));
                sm.logp[tid] += (s ? z1 : z0) - lse;
            }
        }
    }
    __syncthreads();
    if (rank == 0 && tid < NB) out[grp * NB + tid] = sm.logp[tid];
    CLUSTER_ARRIVE(); CLUSTER_WAIT();
}

extern "C" void kernel_launch(void* const* d_in, const int* in_sizes, int n_in,
                              void* d_out, int out_size)
{
    const int*   x    = (const int*)d_in[0];
    const float* Winh = (const float*)d_in[1];
    const float* Winv = (const float*)d_in[2];
    const float* Wch  = (const float*)d_in[3];
    const float* bch  = (const float*)d_in[4];
    const float* Wcv  = (const float*)d_in[5];
    const float* Wout = (const float*)d_in[6];
    const float* bout = (const float*)d_in[7];
    float* out = (float*)d_out;

    prep_wch<<<UU * UU / 4 / 256, 256>>>(Wch);

    const int smem = (int)sizeof(SM);
    cudaFuncSetAttribute(rnn2d_kernel,
                         cudaFuncAttributeMaxDynamicSharedMemorySize, smem);
    rnn2d_kernel<<<NCTA, NTHR, smem>>>(x, Winh, Winv, Wch, bch, Wcv,
                                       Wout, bout, out);
}